// round 5
// baseline (speedup 1.0000x reference)
#include <cuda_runtime.h>
#include <cuda_bf16.h>
#include <math.h>

// Problem constants
#define BATCH 256
#define DDIM  511
#define HDIM  5120
#define QPARTS 2        // CTAs per batch for the quadratic form
#define SPLITK 8        // K-splits for GEMM2
#define LDC2   512      // padded leading dim for GEMM2 partials

// Scratch (device globals; no allocation allowed)
__device__ float g_h[BATCH * HDIM];                      // hidden [256,5120]
__device__ float g_phi[BATCH * DDIM];                    // phi [256,511]
__device__ float g_phi_part[SPLITK * BATCH * LDC2];      // split-K partials
__device__ float g_quadp[BATCH * QPARTS];                // partial quad forms

// ---------------------------------------------------------------------------
// Packed fp32x2 helpers (Blackwell f32x2 SIMD on the FMA pipe).
// fma.rn.f32x2 rounds identically to scalar fmaf -> bit-exact fp32 numerics.
// ---------------------------------------------------------------------------
__device__ __forceinline__ void fma2(unsigned long long& d,
                                     unsigned long long a,
                                     unsigned long long b) {
    asm("fma.rn.f32x2 %0, %1, %2, %0;" : "+l"(d) : "l"(a), "l"(b));
}
__device__ __forceinline__ float2 unpack2(unsigned long long v) {
    float lo, hi;
    asm("mov.b64 {%0, %1}, %2;" : "=f"(lo), "=f"(hi) : "l"(v));
    return make_float2(lo, hi);
}

// ---------------------------------------------------------------------------
// f32x2 tiled GEMM: C[M,N] = act(A[M,K] * B[N,K]^T (+ bias))
// A tile stored DUPLICATED in smem (float2 {a,a}): mainloop per kk is
//   2x LDS.128 (ra pairs) + 2x LDS.128 (rb pairs) + 16x FMA2  (80% FMA2)
// Requires TM == 4 (ra loaded as 2 ulonglong2) and TN == 8.
// PARTIAL: split-K over gridDim.z, store raw partials with leading dim ldc.
// ---------------------------------------------------------------------------
template<int BM, int BN, int BK, bool RELU, bool PARTIAL>
__global__ __launch_bounds__((BM/4)*(BN/8))
void gemm2x_kernel(const float* __restrict__ A,
                   const float* __restrict__ B,
                   const float* __restrict__ bias,
                   float* __restrict__ C,
                   int M, int N, int K, int kPerSplit, int ldc)
{
    constexpr int TM = 4, TN = 8, TN2 = TN / 2;
    constexpr int NT = (BM/TM) * (BN/TN);

    __shared__ __align__(16) float2 As2[BK][BM];   // duplicated pairs {a,a}
    __shared__ __align__(16) float  Bs[BK][BN];

    const int tid = threadIdx.x;
    const int tx  = tid % (BN/TN);
    const int ty  = tid / (BN/TN);

    const int m0 = blockIdx.y * BM;
    const int n0 = blockIdx.x * BN;

    const int kbeg = blockIdx.z * kPerSplit;
    const int kend = min(kbeg + kPerSplit, K);

    unsigned long long acc[TM][TN2];
    #pragma unroll
    for (int i = 0; i < TM; i++)
        #pragma unroll
        for (int j = 0; j < TN2; j++)
            acc[i][j] = 0ull;

    for (int k0 = kbeg; k0 < kend; k0 += BK) {
        // As2[kk][i] = {A[m0+i][k0+kk], same}
        #pragma unroll
        for (int idx = tid; idx < BM * BK; idx += NT) {
            int kk = idx % BK, i = idx / BK;
            int m = m0 + i, k = k0 + kk;
            float v = 0.0f;
            if (m < M && k < kend) v = A[(size_t)m * K + k];
            As2[kk][i] = make_float2(v, v);
        }
        // Bs[kk][j] = B[n0+j][k0+kk]
        #pragma unroll
        for (int idx = tid; idx < BN * BK; idx += NT) {
            int kk = idx % BK, j = idx / BK;
            int n = n0 + j, k = k0 + kk;
            float v = 0.0f;
            if (n < N && k < kend) v = B[(size_t)n * K + k];
            Bs[kk][j] = v;
        }
        __syncthreads();

        #pragma unroll
        for (int kk = 0; kk < BK; kk++) {
            // ra: 4 duplicated pairs via 2x LDS.128
            const ulonglong2 a01 =
                *(const ulonglong2*)(&As2[kk][ty * TM]);
            const ulonglong2 a23 =
                *(const ulonglong2*)(&As2[kk][ty * TM + 2]);
            unsigned long long ra[TM] = { a01.x, a01.y, a23.x, a23.y };

            // rb: 4 packed pairs via 2x LDS.128 (pairs pre-packed in smem)
            const ulonglong2 b01 =
                *(const ulonglong2*)(&Bs[kk][tx * TN]);
            const ulonglong2 b23 =
                *(const ulonglong2*)(&Bs[kk][tx * TN + 4]);
            unsigned long long rb[TN2] = { b01.x, b01.y, b23.x, b23.y };

            #pragma unroll
            for (int i = 0; i < TM; i++)
                #pragma unroll
                for (int j = 0; j < TN2; j++)
                    fma2(acc[i][j], ra[i], rb[j]);
        }
        __syncthreads();
    }

    // Store
    #pragma unroll
    for (int i = 0; i < TM; i++) {
        const int m = m0 + ty * TM + i;
        if (m >= M) continue;
        #pragma unroll
        for (int j = 0; j < TN2; j++) {
            const int n = n0 + tx * TN + 2 * j;
            const float2 v = unpack2(acc[i][j]);
            if (PARTIAL) {
                float* __restrict__ Cz = C + (size_t)blockIdx.z * M * ldc;
                if (n     < N) Cz[(size_t)m * ldc + n]     = v.x;
                if (n + 1 < N) Cz[(size_t)m * ldc + n + 1] = v.y;
            } else {
                if (n < N) {
                    float a = v.x + bias[n];
                    if (RELU) a = fmaxf(a, 0.0f);
                    C[(size_t)m * ldc + n] = a;
                }
                if (n + 1 < N) {
                    float a = v.y + bias[n + 1];
                    if (RELU) a = fmaxf(a, 0.0f);
                    C[(size_t)m * ldc + n + 1] = a;
                }
            }
        }
    }
}

// ---------------------------------------------------------------------------
// Split-K reduce: phi[m][n] = sum_z part[z][m][n] + bias[n]
// ---------------------------------------------------------------------------
__global__ __launch_bounds__(256)
void reduce_phi_kernel(const float* __restrict__ bias)
{
    const int idx = blockIdx.x * 256 + threadIdx.x;
    if (idx >= BATCH * DDIM) return;
    const int m = idx / DDIM;
    const int n = idx % DDIM;
    float s = bias[n];
    #pragma unroll
    for (int z = 0; z < SPLITK; z++)
        s += g_phi_part[(size_t)z * BATCH * LDC2 + (size_t)m * LDC2 + n];
    g_phi[idx] = s;
}

// ---------------------------------------------------------------------------
// Batched quadratic form (partial): QPARTS CTAs per batch, warp-per-row,
// float4 streaming loads with per-row alignment fixup.
// ---------------------------------------------------------------------------
__global__ __launch_bounds__(256)
void quad_kernel(const float* __restrict__ Minv)
{
    const int b    = blockIdx.x / QPARTS;
    const int part = blockIdx.x % QPARTS;
    const float* __restrict__ Mb = Minv + (size_t)b * DDIM * DDIM;
    const float* __restrict__ pb = g_phi + (size_t)b * DDIM;

    __shared__ float ph[DDIM];
    const int tid = threadIdx.x;
    for (int i = tid; i < DDIM; i += 256) ph[i] = pb[i];
    __syncthreads();

    const int warp = tid >> 5;
    const int lane = tid & 31;

    float acc = 0.0f;
    for (int i = part * 8 + warp; i < DDIM; i += QPARTS * 8) {
        const float* __restrict__ row = Mb + (size_t)i * DDIM;
        float p = 0.0f;

        const int head = (4 - (int)(((size_t)row >> 2) & 3)) & 3;
        if (lane < head)
            p = fmaf(__ldcs(row + lane), ph[lane], p);

        const int nvec = (DDIM - head) >> 2;
        const float4* __restrict__ rv = (const float4*)(row + head);
        #pragma unroll 4
        for (int v = lane; v < nvec; v += 32) {
            const float4 m = __ldcs(rv + v);
            const int j = head + 4 * v;
            p = fmaf(m.x, ph[j    ], p);
            p = fmaf(m.y, ph[j + 1], p);
            p = fmaf(m.z, ph[j + 2], p);
            p = fmaf(m.w, ph[j + 3], p);
        }

        const int tbase = head + 4 * nvec;
        if (tbase + lane < DDIM)
            p = fmaf(__ldcs(row + tbase + lane), ph[tbase + lane], p);

        acc = fmaf(p, ph[i], acc);
    }

    #pragma unroll
    for (int o = 16; o; o >>= 1)
        acc += __shfl_xor_sync(0xFFFFFFFFu, acc, o);

    __shared__ float wsum[8];
    if (lane == 0) wsum[warp] = acc;
    __syncthreads();
    if (tid == 0) {
        float s = 0.0f;
        #pragma unroll
        for (int w = 0; w < 8; w++) s += wsum[w];
        g_quadp[b * QPARTS + part] = s;
    }
}

// ---------------------------------------------------------------------------
// Epilogue: combine quad parts; phi_n = phi/sqrt(quad); tiny MLP -> lambda;
// out = sign(phi_n) * max(0, |phi_n| - 0.1*lambda)
// ---------------------------------------------------------------------------
__global__ __launch_bounds__(256)
void epilogue_kernel(const float* __restrict__ st_w1,
                     const float* __restrict__ st_b1,
                     const float* __restrict__ st_w2,
                     const float* __restrict__ st_b2,
                     float* __restrict__ out)
{
    const int idx = blockIdx.x * 256 + threadIdx.x;
    if (idx >= BATCH * DDIM) return;
    const int b = idx / DDIM;

    float q = 0.0f;
    #pragma unroll
    for (int p = 0; p < QPARTS; p++) q += g_quadp[b * QPARTS + p];

    const float inv = rsqrtf(q);
    const float x   = g_phi[idx] * inv;

    float lam = st_b2[0];
    #pragma unroll
    for (int k = 0; k < 5; k++)
        lam = fmaf(fmaxf(fmaf(x, st_w1[k], st_b1[k]), 0.0f), st_w2[k], lam);
    lam = fabsf(lam) * 0.1f;

    const float a = fabsf(x) - lam;
    out[idx] = (a > 0.0f) ? copysignf(a, x) : 0.0f;
}

// ---------------------------------------------------------------------------
// Launch
// ---------------------------------------------------------------------------
extern "C" void kernel_launch(void* const* d_in, const int* in_sizes, int n_in,
                              void* d_out, int out_size)
{
    // 0 theta_12, 1 s_12, 2 w_12, 3 inv_Theta_11, 4 Theta, 5 col,
    // 6 phi_w1, 7 phi_b1, 8 phi_w2, 9 phi_b2, 10 st_w1, 11 st_b1,
    // 12 st_w2, 13 st_b2
    const float* theta12 = (const float*)d_in[0];
    const float* invT    = (const float*)d_in[3];
    const float* phi_w1  = (const float*)d_in[6];
    const float* phi_b1  = (const float*)d_in[7];
    const float* phi_w2  = (const float*)d_in[8];
    const float* phi_b2  = (const float*)d_in[9];
    const float* st_w1   = (const float*)d_in[10];
    const float* st_b1   = (const float*)d_in[11];
    const float* st_w2   = (const float*)d_in[12];
    const float* st_b2   = (const float*)d_in[13];
    float* out = (float*)d_out;

    float* hbuf;   cudaGetSymbolAddress((void**)&hbuf, g_h);
    float* pbuf;   cudaGetSymbolAddress((void**)&pbuf, g_phi_part);

    // GEMM1: h = relu(theta12 @ phi_w1^T + b1)  [256,5120], K=511
    // BM=32, BN=128 -> 128 threads, grid 40x8 = 320 CTAs (2/SM, 8 warps/SM)
    {
        dim3 grid(HDIM / 128, BATCH / 32, 1);
        gemm2x_kernel<32, 128, 16, true, false><<<grid, 128>>>(
            theta12, phi_w1, phi_b1, hbuf, BATCH, HDIM, DDIM, DDIM, HDIM);
    }
    // GEMM2 (split-K): partials = h @ phi_w2^T  [256,511], K=5120
    // BM=64, BN=64 -> 128 threads, grid 8x4x8 = 256 CTAs
    {
        dim3 grid((DDIM + 63) / 64, BATCH / 64, SPLITK);
        gemm2x_kernel<64, 64, 16, false, true><<<grid, 128>>>(
            hbuf, phi_w2, nullptr, pbuf, BATCH, DDIM, HDIM, HDIM / SPLITK, LDC2);
    }
    // reduce partials + bias -> phi
    {
        int n = BATCH * DDIM;
        reduce_phi_kernel<<<(n + 255) / 256, 256>>>(phi_b2);
    }
    // quad partials: phi^T invT phi
    quad_kernel<<<BATCH * QPARTS, 256>>>(invT);

    // epilogue
    {
        int n = BATCH * DDIM;
        epilogue_kernel<<<(n + 255) / 256, 256>>>(st_w1, st_b1, st_w2, st_b2, out);
    }
}

// round 9
// speedup vs baseline: 2.2225x; 2.2225x over previous
#include <cuda_runtime.h>
#include <cuda_bf16.h>
#include <math.h>

// Problem constants
#define BATCH 256
#define DDIM  511
#define HDIM  5120
#define QPARTS 4        // CTAs per batch for the quadratic form
#define SPLITK 8        // K-splits for GEMM2
#define LDC2   512      // padded leading dim for GEMM2 partials

// Scratch (device globals; no allocation allowed)
__device__ float g_h[BATCH * HDIM];                      // hidden [256,5120]
__device__ float g_phi[BATCH * DDIM];                    // phi [256,511]
__device__ float g_phi_part[SPLITK * BATCH * LDC2];      // split-K partials
__device__ float g_quadp[BATCH * QPARTS];                // partial quad forms

// ---------------------------------------------------------------------------
// Packed fp32x2 helpers (Blackwell f32x2 SIMD on the FMA pipe).
// fma.rn.f32x2 rounds identically to scalar fmaf -> bit-exact fp32 numerics.
// ---------------------------------------------------------------------------
__device__ __forceinline__ void fma2(unsigned long long& d,
                                     unsigned long long a,
                                     unsigned long long b) {
    asm("fma.rn.f32x2 %0, %1, %2, %0;" : "+l"(d) : "l"(a), "l"(b));
}
__device__ __forceinline__ float2 unpack2(unsigned long long v) {
    float lo, hi;
    asm("mov.b64 {%0, %1}, %2;" : "=f"(lo), "=f"(hi) : "l"(v));
    return make_float2(lo, hi);
}

// ---------------------------------------------------------------------------
// f32x2 tiled GEMM: C[M,N] = act(A[M,K] * B[N,K]^T (+ bias))
// Conflict-engineered smem:
//   As2 rows padded +2 float2 (stride 272B): STS.64 stores 2-way worst case,
//     mainloop LDS.128 reads broadcast (all lanes same address per phase).
//   Bs rows padded +4 float (stride 528B/272B): STS.32 stores 2-way worst
//     case; mainloop LDS.128 conflict-free (thread cols = two float4 groups
//     at tx*4 and BN/2+tx*4 -> lanes cover contiguous 16B chunks).
// Mainloop per kk: 2x LDS.128 (ra) + 2x LDS.128 (rb) + 16x FMA2 (80% FMA2).
// PARTIAL: split-K over gridDim.z, store raw partials with leading dim ldc.
// ---------------------------------------------------------------------------
template<int BM, int BN, int BK, bool RELU, bool PARTIAL>
__global__ __launch_bounds__((BM/4)*(BN/8))
void gemm2x_kernel(const float* __restrict__ A,
                   const float* __restrict__ B,
                   const float* __restrict__ bias,
                   float* __restrict__ C,
                   int M, int N, int K, int kPerSplit, int ldc)
{
    constexpr int TM = 4, TN = 8;
    constexpr int NX = BN / TN;           // threads along N
    constexpr int NT = (BM/TM) * NX;
    constexpr int BMP = BM + 2;           // padded As2 row (float2 units)
    constexpr int BNP = BN + 4;           // padded Bs row (float units)

    __shared__ __align__(16) float2 As2[BK][BMP];  // duplicated pairs {a,a}
    __shared__ __align__(16) float  Bs[BK][BNP];

    const int tid = threadIdx.x;
    const int tx  = tid % NX;
    const int ty  = tid / NX;

    const int m0 = blockIdx.y * BM;
    const int n0 = blockIdx.x * BN;

    const int kbeg = blockIdx.z * kPerSplit;
    const int kend = min(kbeg + kPerSplit, K);

    unsigned long long acc[TM][4];
    #pragma unroll
    for (int i = 0; i < TM; i++)
        #pragma unroll
        for (int j = 0; j < 4; j++)
            acc[i][j] = 0ull;

    for (int k0 = kbeg; k0 < kend; k0 += BK) {
        // As2[kk][i] = {A[m0+i][k0+kk], same}; kk fast in tid (coalesced LDG)
        #pragma unroll
        for (int idx = tid; idx < BM * BK; idx += NT) {
            int kk = idx % BK, i = idx / BK;
            int m = m0 + i, k = k0 + kk;
            float v = 0.0f;
            if (m < M && k < kend) v = A[(size_t)m * K + k];
            As2[kk][i] = make_float2(v, v);
        }
        // Bs[kk][j] = B[n0+j][k0+kk]; kk fast in tid (coalesced LDG)
        #pragma unroll
        for (int idx = tid; idx < BN * BK; idx += NT) {
            int kk = idx % BK, j = idx / BK;
            int n = n0 + j, k = k0 + kk;
            float v = 0.0f;
            if (n < N && k < kend) v = B[(size_t)n * K + k];
            Bs[kk][j] = v;
        }
        __syncthreads();

        #pragma unroll
        for (int kk = 0; kk < BK; kk++) {
            // ra: 4 duplicated pairs via 2x LDS.128 (broadcast per phase)
            const ulonglong2 a01 = *(const ulonglong2*)(&As2[kk][ty * TM]);
            const ulonglong2 a23 = *(const ulonglong2*)(&As2[kk][ty * TM + 2]);
            const unsigned long long ra[TM] = { a01.x, a01.y, a23.x, a23.y };

            // rb: 2 float4 groups (conflict-free: lanes contiguous 16B chunks)
            const ulonglong2 blo = *(const ulonglong2*)(&Bs[kk][tx * 4]);
            const ulonglong2 bhi = *(const ulonglong2*)(&Bs[kk][BN/2 + tx * 4]);
            const unsigned long long rb[4] = { blo.x, blo.y, bhi.x, bhi.y };

            #pragma unroll
            for (int i = 0; i < TM; i++)
                #pragma unroll
                for (int j = 0; j < 4; j++)
                    fma2(acc[i][j], ra[i], rb[j]);
        }
        __syncthreads();
    }

    // Store: cols for pair j: j<2 -> n0 + tx*4 + 2j(+1); j>=2 -> +BN/2
    #pragma unroll
    for (int i = 0; i < TM; i++) {
        const int m = m0 + ty * TM + i;
        if (m >= M) continue;
        #pragma unroll
        for (int j = 0; j < 4; j++) {
            const int base = (j < 2) ? (n0 + tx * 4 + 2 * j)
                                     : (n0 + BN/2 + tx * 4 + 2 * (j - 2));
            const float2 v = unpack2(acc[i][j]);
            if (PARTIAL) {
                float* __restrict__ Cz = C + (size_t)blockIdx.z * M * ldc;
                if (base     < N) Cz[(size_t)m * ldc + base]     = v.x;
                if (base + 1 < N) Cz[(size_t)m * ldc + base + 1] = v.y;
            } else {
                if (base < N) {
                    float a = v.x + bias[base];
                    if (RELU) a = fmaxf(a, 0.0f);
                    C[(size_t)m * ldc + base] = a;
                }
                if (base + 1 < N) {
                    float a = v.y + bias[base + 1];
                    if (RELU) a = fmaxf(a, 0.0f);
                    C[(size_t)m * ldc + base + 1] = a;
                }
            }
        }
    }
}

// ---------------------------------------------------------------------------
// Split-K reduce: phi[m][n] = sum_z part[z][m][n] + bias[n]
// ---------------------------------------------------------------------------
__global__ __launch_bounds__(256)
void reduce_phi_kernel(const float* __restrict__ bias)
{
    const int idx = blockIdx.x * 256 + threadIdx.x;
    if (idx >= BATCH * DDIM) return;
    const int m = idx / DDIM;
    const int n = idx % DDIM;
    float s = bias[n];
    #pragma unroll
    for (int z = 0; z < SPLITK; z++)
        s += g_phi_part[(size_t)z * BATCH * LDC2 + (size_t)m * LDC2 + n];
    g_phi[idx] = s;
}

// ---------------------------------------------------------------------------
// Batched quadratic form, SYMMETRIC lower-triangle only. inv_Theta_11 is
// bit-exactly symmetric (M_ij and M_ji sum identical products in identical
// k-order in the reference einsum). Reads HALF the matrix (134MB vs 267MB):
//   quad = 2*sum_{j<i} M_ij p_i p_j + sum_i M_ii p_i^2
// QPARTS CTAs per batch; warp-per-row (rows interleaved mod 32 for balance);
// float4 __ldcs streaming with per-row alignment fixup.
// ---------------------------------------------------------------------------
__global__ __launch_bounds__(256)
void quad_kernel(const float* __restrict__ Minv)
{
    const int b    = blockIdx.x / QPARTS;
    const int part = blockIdx.x % QPARTS;
    const float* __restrict__ Mb = Minv + (size_t)b * DDIM * DDIM;
    const float* __restrict__ pb = g_phi + (size_t)b * DDIM;

    __shared__ float ph[DDIM];
    const int tid = threadIdx.x;
    for (int i = tid; i < DDIM; i += 256) ph[i] = pb[i];
    __syncthreads();

    const int warp = tid >> 5;
    const int lane = tid & 31;
    const int G    = QPARTS * 8;

    float accOff  = 0.0f;   // sum p_i * (partial dot over j<i)
    float accDiag = 0.0f;   // lane 0: sum M_ii p_i^2

    for (int i = part * 8 + warp; i < DDIM; i += G) {
        const float* __restrict__ row = Mb + (size_t)i * DDIM;
        const float pi = ph[i];
        float sub = 0.0f;

        int head = (4 - (int)(((size_t)row >> 2) & 3)) & 3;
        if (head > i) head = i;
        if (lane < head)
            sub = fmaf(__ldcs(row + lane), ph[lane], sub);

        const int nvec = (i - head) >> 2;
        const float4* __restrict__ rv = (const float4*)(row + head);
        #pragma unroll 4
        for (int v = lane; v < nvec; v += 32) {
            const float4 m = __ldcs(rv + v);
            const int j = head + 4 * v;
            sub = fmaf(m.x, ph[j    ], sub);
            sub = fmaf(m.y, ph[j + 1], sub);
            sub = fmaf(m.z, ph[j + 2], sub);
            sub = fmaf(m.w, ph[j + 3], sub);
        }

        const int tb = head + 4 * nvec;
        if (tb + lane < i)
            sub = fmaf(__ldcs(row + tb + lane), ph[tb + lane], sub);

        accOff = fmaf(pi, sub, accOff);                 // distributed over lanes
        if (lane == 0)
            accDiag = fmaf(__ldg(row + i) * pi, pi, accDiag);
    }

    float acc = 2.0f * accOff + accDiag;
    #pragma unroll
    for (int o = 16; o; o >>= 1)
        acc += __shfl_xor_sync(0xFFFFFFFFu, acc, o);

    __shared__ float wsum[8];
    if (lane == 0) wsum[warp] = acc;
    __syncthreads();
    if (tid == 0) {
        float s = 0.0f;
        #pragma unroll
        for (int w = 0; w < 8; w++) s += wsum[w];
        g_quadp[b * QPARTS + part] = s;
    }
}

// ---------------------------------------------------------------------------
// Epilogue: combine quad parts; phi_n = phi/sqrt(quad); tiny MLP -> lambda;
// out = sign(phi_n) * max(0, |phi_n| - 0.1*lambda)
// ---------------------------------------------------------------------------
__global__ __launch_bounds__(256)
void epilogue_kernel(const float* __restrict__ st_w1,
                     const float* __restrict__ st_b1,
                     const float* __restrict__ st_w2,
                     const float* __restrict__ st_b2,
                     float* __restrict__ out)
{
    const int idx = blockIdx.x * 256 + threadIdx.x;
    if (idx >= BATCH * DDIM) return;
    const int b = idx / DDIM;

    float q = 0.0f;
    #pragma unroll
    for (int p = 0; p < QPARTS; p++) q += g_quadp[b * QPARTS + p];

    const float inv = rsqrtf(q);
    const float x   = g_phi[idx] * inv;

    float lam = st_b2[0];
    #pragma unroll
    for (int k = 0; k < 5; k++)
        lam = fmaf(fmaxf(fmaf(x, st_w1[k], st_b1[k]), 0.0f), st_w2[k], lam);
    lam = fabsf(lam) * 0.1f;

    const float a = fabsf(x) - lam;
    out[idx] = (a > 0.0f) ? copysignf(a, x) : 0.0f;
}

// ---------------------------------------------------------------------------
// Launch
// ---------------------------------------------------------------------------
extern "C" void kernel_launch(void* const* d_in, const int* in_sizes, int n_in,
                              void* d_out, int out_size)
{
    // 0 theta_12, 1 s_12, 2 w_12, 3 inv_Theta_11, 4 Theta, 5 col,
    // 6 phi_w1, 7 phi_b1, 8 phi_w2, 9 phi_b2, 10 st_w1, 11 st_b1,
    // 12 st_w2, 13 st_b2
    const float* theta12 = (const float*)d_in[0];
    const float* invT    = (const float*)d_in[3];
    const float* phi_w1  = (const float*)d_in[6];
    const float* phi_b1  = (const float*)d_in[7];
    const float* phi_w2  = (const float*)d_in[8];
    const float* phi_b2  = (const float*)d_in[9];
    const float* st_w1   = (const float*)d_in[10];
    const float* st_b1   = (const float*)d_in[11];
    const float* st_w2   = (const float*)d_in[12];
    const float* st_b2   = (const float*)d_in[13];
    float* out = (float*)d_out;

    float* hbuf;   cudaGetSymbolAddress((void**)&hbuf, g_h);
    float* pbuf;   cudaGetSymbolAddress((void**)&pbuf, g_phi_part);

    // GEMM1: h = relu(theta12 @ phi_w1^T + b1)  [256,5120], K=511
    // BM=32, BN=128 -> 128 threads, grid 40x8 = 320 CTAs
    {
        dim3 grid(HDIM / 128, BATCH / 32, 1);
        gemm2x_kernel<32, 128, 16, true, false><<<grid, 128>>>(
            theta12, phi_w1, phi_b1, hbuf, BATCH, HDIM, DDIM, DDIM, HDIM);
    }
    // GEMM2 (split-K): partials = h @ phi_w2^T  [256,511], K=5120
    // BM=64, BN=64 -> 128 threads, grid 8x4x8 = 256 CTAs
    {
        dim3 grid((DDIM + 63) / 64, BATCH / 64, SPLITK);
        gemm2x_kernel<64, 64, 16, false, true><<<grid, 128>>>(
            hbuf, phi_w2, nullptr, pbuf, BATCH, DDIM, HDIM, HDIM / SPLITK, LDC2);
    }
    // reduce partials + bias -> phi
    {
        int n = BATCH * DDIM;
        reduce_phi_kernel<<<(n + 255) / 256, 256>>>(phi_b2);
    }
    // quad partials: phi^T invT phi (lower triangle x2 + diagonal)
    quad_kernel<<<BATCH * QPARTS, 256>>>(invT);

    // epilogue
    {
        int n = BATCH * DDIM;
        epilogue_kernel<<<(n + 255) / 256, 256>>>(st_w1, st_b1, st_w2, st_b2, out);
    }
}